// round 14
// baseline (speedup 1.0000x reference)
#include <cuda_runtime.h>

// DynamicPatching: B=32, C=64, T=8192, S=64.
// out[b][s][c][p] = (p < len_bs) ? tensor[b][c][start_bs + p] : 0
// Output (B, S, C, max_len) row-major.
//
// 2 rows/warp @ 8 CTAs/SM (R12 occupancy) + region-split hot loops (R10 ALU
// diet): copy loop has only fully-valid chunks (unpredicated loads, two-phase
// batched), zero loop is a store-only STG.128 stream; the single boundary
// chunk and head/tail are hoisted predicated scalars. Loads evict-normal,
// stores evict-first.

#define PB 32
#define PC 64
#define PT 8192
#define PS 64

__device__ __forceinline__ void stcs4(float* p, float4 v) {
    asm volatile("st.global.cs.v4.f32 [%0], {%1,%2,%3,%4};"
                 :: "l"(p), "f"(v.x), "f"(v.y), "f"(v.z), "f"(v.w) : "memory");
}
__device__ __forceinline__ void stcs1(float* p, float v) {
    asm volatile("st.global.cs.f32 [%0], %1;" :: "l"(p), "f"(v) : "memory");
}

__global__ void __launch_bounds__(256, 8)
dynamic_patching_kernel(const float* __restrict__ tensor,
                        const int*   __restrict__ cps,   // (B, S+1) int32
                        float*       __restrict__ out,
                        int max_len)
{
    // 4 blocks per (b,s): each block covers 16 of the 64 channels.
    const int bs = blockIdx.x >> 2;
    const int q  = blockIdx.x & 3;
    const int b  = bs >> 6;              // / PS
    const int s  = bs & (PS - 1);        // % PS

    const int start = __ldg(cps + b * (PS + 1) + s);
    const int len   = __ldg(cps + b * (PS + 1) + s + 1) - start;

    const int wid  = threadIdx.x >> 5;   // 0..7
    const int lane = threadIdx.x & 31;

    const int cbase = q * 16 + wid * 2;  // warp's first channel (owns 2 rows)

    const float* __restrict__ row0 = tensor + ((size_t)b * PC) * PT + start;
    const long long out_base = (long long)bs * PC * (long long)max_len;

    // Per-row invariants.
    //  p0: head scalars to reach 16B alignment (0..3)
    //  kf: # fully-valid chunks; kz: first pure-zero chunk; nv: total chunks
    const float* src[2];
    float*       dst[2];
    int p0[2], kf[2], kz[2], nv[2];
    int kfmax = 0, nzmax = 0;

    #pragma unroll
    for (int r = 0; r < 2; ++r) {
        const int c = cbase + r;
        src[r] = row0 + (size_t)c * PT;
        const long long row_idx = out_base + (long long)c * (long long)max_len;
        dst[r] = out + row_idx;
        p0[r]  = (int)((4 - (row_idx & 3)) & 3);
        nv[r]  = (max_len - p0[r]) >> 2;
        const int lp = len - p0[r];
        kf[r] = (lp > 0) ? (lp >> 2) : 0;
        kz[r] = (lp > 0) ? min((lp + 3) >> 2, nv[r]) : 0;
        kfmax = max(kfmax, kf[r]);
        nzmax = max(nzmax, nv[r] - kz[r]);
    }

    // Hoisted edge scalars per row: head (<p0), boundary chunk (<=4),
    // tail (<4). All predicated; cold path.
    #pragma unroll
    for (int r = 0; r < 2; ++r) {
        if (lane < p0[r])
            stcs1(dst[r] + lane, (lane < len) ? src[r][lane] : 0.0f);
        if (kf[r] < kz[r] && lane < 4) {            // boundary chunk exists
            const int p = p0[r] + (kf[r] << 2) + lane;
            stcs1(dst[r] + p, (p < len) ? src[r][p] : 0.0f);
        }
        const int tp = p0[r] + (nv[r] << 2) + lane;
        if (tp < max_len)
            stcs1(dst[r] + tp, (tp < len) ? src[r][tp] : 0.0f);
    }

    // Copy loop: fully-valid chunks only. Phase 1: 8 unpredicated loads
    // across 2 rows; phase 2: 2 STG.128. Sole guard: k < kf[r].
    for (int kb = 0; kb < kfmax; kb += 32) {
        const int k = kb + lane;
        float4 v[2];
        #pragma unroll
        for (int r = 0; r < 2; ++r) {
            if (k < kf[r]) {
                const float* sp = src[r] + p0[r] + (k << 2);
                v[r].x = sp[0];
                v[r].y = sp[1];
                v[r].z = sp[2];
                v[r].w = sp[3];
            }
        }
        #pragma unroll
        for (int r = 0; r < 2; ++r) {
            if (k < kf[r])
                stcs4(dst[r] + p0[r] + (k << 2), v[r]);
        }
    }

    // Zero loop: store-only STG.128 stream over chunks [kz, nv).
    const float4 z4 = make_float4(0.0f, 0.0f, 0.0f, 0.0f);
    for (int kb = 0; kb < nzmax; kb += 32) {
        const int k = kb + lane;
        #pragma unroll
        for (int r = 0; r < 2; ++r) {
            const int ck = kz[r] + k;
            if (ck < nv[r])
                stcs4(dst[r] + p0[r] + (ck << 2), z4);
        }
    }
}

extern "C" void kernel_launch(void* const* d_in, const int* in_sizes, int n_in,
                              void* d_out, int out_size)
{
    const float* tensor = (const float*)d_in[0];
    const int*   cps    = (const int*)d_in[1];
    float*       out    = (float*)d_out;

    const int max_len = out_size / (PB * PS * PC);

    dynamic_patching_kernel<<<PB * PS * 4, 256>>>(tensor, cps, out, max_len);
}

// round 15
// speedup vs baseline: 1.1544x; 1.1544x over previous
#include <cuda_runtime.h>

// DynamicPatching: B=32, C=64, T=8192, S=64.
// out[b][s][c][p] = (p < len_bs) ? tensor[b][c][start_bs + p] : 0
// Output (B, S, C, max_len) row-major.
//
// Champion two-phase structure (warp owns 4 rows, 16 batched loads -> 4
// STG.128) with SHARED-ALIGNMENT row grouping: warp owns rows
// {c, c+8, c+16, c+24}. Row offsets differ by multiples of 4*max_len, so all
// 4 rows share one alignment class -> p0/nv are warp scalars, and the 4
// element-mask predicates per k-step are shared across all 4 rows
// (4 ISETPs per 16 loads instead of 16). Loads evict-normal, stores .cs.

#define PB 32
#define PC 64
#define PT 8192
#define PS 64

__device__ __forceinline__ void stcs4(float* p, float4 v) {
    asm volatile("st.global.cs.v4.f32 [%0], {%1,%2,%3,%4};"
                 :: "l"(p), "f"(v.x), "f"(v.y), "f"(v.z), "f"(v.w) : "memory");
}
__device__ __forceinline__ void stcs1(float* p, float v) {
    asm volatile("st.global.cs.f32 [%0], %1;" :: "l"(p), "f"(v) : "memory");
}

__global__ void __launch_bounds__(256, 6)
dynamic_patching_kernel(const float* __restrict__ tensor,
                        const int*   __restrict__ cps,   // (B, S+1) int32
                        float*       __restrict__ out,
                        int max_len)
{
    // 2 blocks per (b,s): each covers 32 of the 64 channels.
    const int bs   = blockIdx.x >> 1;
    const int half = blockIdx.x & 1;
    const int b    = bs >> 6;            // / PS
    const int s    = bs & (PS - 1);      // % PS

    const int start = __ldg(cps + b * (PS + 1) + s);
    const int len   = __ldg(cps + b * (PS + 1) + s + 1) - start;

    const int wid  = threadIdx.x >> 5;   // 0..7
    const int lane = threadIdx.x & 31;

    // Warp owns rows c0, c0+8, c0+16, c0+24 (same alignment class).
    const int c0 = half * 32 + wid;

    const float* __restrict__ src0 = tensor + ((b * PC + c0) << 13) + start;
    const int dbase = (bs * PC + c0) * max_len;      // fits int32 (< 2^25)
    float* __restrict__ dst0 = out + dbase;

    const int rs_src = 8 << 13;          // 8 channels of src stride (floats)
    const int rs_dst = 8 * max_len;      // 8 rows of dst stride (floats)

    // Warp-uniform alignment: all 4 rows share p0 / nv.
    const int p0 = (4 - (dbase & 3)) & 3;
    const int nv = (max_len - p0) >> 2;

    // Heads (< p0) and tails (< 4), hoisted. Shared p0/nv across rows.
    #pragma unroll
    for (int r = 0; r < 4; ++r) {
        const float* sr = src0 + r * rs_src;
        float*       dr = dst0 + r * rs_dst;
        if (lane < p0)
            stcs1(dr + lane, (lane < len) ? sr[lane] : 0.0f);
        const int p = p0 + (nv << 2) + lane;
        if (p < max_len)
            stcs1(dr + p, (p < len) ? sr[p] : 0.0f);
    }

    // Hot loop: two-phase. Masks m0..m3 computed ONCE per k-step and shared
    // by all 4 rows' loads. Phase 1: 16 independent predicated loads.
    // Phase 2: 4 STG.128.
    for (int kb = 0; kb < nv; kb += 32) {
        const int k = kb + lane;
        if (k < nv) {
            const int p  = p0 + (k << 2);
            const bool m0 = (p + 0) < len;
            const bool m1 = (p + 1) < len;
            const bool m2 = (p + 2) < len;
            const bool m3 = (p + 3) < len;

            float4 v[4];
            #pragma unroll
            for (int r = 0; r < 4; ++r) {
                const float* sp = src0 + r * rs_src + p;
                v[r] = make_float4(0.0f, 0.0f, 0.0f, 0.0f);
                if (m0) v[r].x = sp[0];
                if (m1) v[r].y = sp[1];
                if (m2) v[r].z = sp[2];
                if (m3) v[r].w = sp[3];
            }
            #pragma unroll
            for (int r = 0; r < 4; ++r)
                stcs4(dst0 + r * rs_dst + p, v[r]);
        }
    }
}

extern "C" void kernel_launch(void* const* d_in, const int* in_sizes, int n_in,
                              void* d_out, int out_size)
{
    const float* tensor = (const float*)d_in[0];
    const int*   cps    = (const int*)d_in[1];
    float*       out    = (float*)d_out;

    const int max_len = out_size / (PB * PS * PC);

    dynamic_patching_kernel<<<PB * PS * 2, 256>>>(tensor, cps, out, max_len);
}